// round 4
// baseline (speedup 1.0000x reference)
#include <cuda_runtime.h>
#include <cuda_bf16.h>

typedef unsigned long long u64;
typedef unsigned int u32;
typedef unsigned char u8;

#define NN 32
#define CO 256
#define HH 32
#define WW 32
#define PIX 1024
#define JCH 36
#define TOTAL (NN * CO * PIX)

// ---------------- static device scratch (no allocation) ----------------
__device__ u32 gXc[NN * PIX * 8];                 // per-pixel channel sign packs (256 bits)
__device__ u64 gWt[2 * 18 * 256 * 2];             // weights, chunk-pair interleaved [conv][j2][o][2]
__device__ u8  gBase[2 * 256 * 9 * JCH];          // base_j per (conv,o,cls,j)
__device__ short gAcc[TOTAL];                     // conv1 accumulator
__device__ float gS[CO], gT[CO];                  // current BN affine: y = a*S + T
__device__ u64 gIsum[CO], gIsq[CO];               // integer stats (conv1), two's complement
__device__ double gDsum[CO], gDsq[CO];            // float stats (conv2 + residual)
__device__ float gReg;                            // 3 * r_const

// chunk j covers features f in [64j, 64j+64), f = c*9 + s; fixed s -> contiguous c range
__device__ __forceinline__ void fieldCS(int j, int s, int& lo, int& len) {
    lo = (64 * j - s + 8) / 9;                    // ceil; numerator >= 0 except j=0 handled (-> 0)
    int hi = (64 * j + 63 - s) / 9;
    if (hi > 255) hi = 255;
    len = hi - lo + 1;
}

// ---------------- setup: zero stats, r_const, weight pack + base tables ----------------
__global__ void k_setup(const float* __restrict__ w1, const float* __restrict__ w2) {
    int t = blockIdx.x * 256 + threadIdx.x;       // grid: 2 blocks x 256
    if (t < 256) { gIsum[t] = 0ull; gIsq[t] = 0ull; gDsum[t] = 0.0; gDsq[t] = 0.0; }
    if (t == 0) {
        // (q-psum)^2 == [nM_j(class) odd]  -> data-independent regularizer
        const int cnt[9] = {1, 30, 1, 30, 900, 30, 1, 30, 1};
        double r = 0.0;
        for (int j = 0; j < JCH; j++)
            for (int cls = 0; cls < 9; cls++) {
                int ch = cls / 3, cw = cls % 3;
                int nM = 0;
                for (int s = 0; s < 9; s++) {
                    int lo, len; fieldCS(j, s, lo, len);
                    int ih = s / 3, iw = s % 3;
                    bool valid = !((ch == 0 && ih == 0) || (ch == 2 && ih == 2) ||
                                   (cw == 0 && iw == 0) || (cw == 2 && iw == 2));
                    if (valid) nM += len;
                }
                if (nM & 1) r += (double)cnt[cls];
            }
        gReg = (float)(3.0 * r / 1024.0);
    }
    if (t < 512) {
        int conv = t >> 8, o = t & 255;
        const float* w = conv ? w2 : w1;
        for (int j = 0; j < JCH; j++) {
            u64 word = 0; int pos = 0;
            int fpc[9], lens[9];
            for (int s = 0; s < 9; s++) {
                int lo, len; fieldCS(j, s, lo, len);
                lens[s] = len;
                u32 f = 0;
                for (int i = 0; i < len; i++)
                    if (w[(size_t)o * 2304 + (size_t)(lo + i) * 9 + s] < 0.f) f |= 1u << i;
                fpc[s] = __popc(f);
                word |= ((u64)f) << pos;
                pos += len;
            }
            gWt[(((size_t)conv * 18 + (j >> 1)) * 256 + o) * 2 + (j & 1)] = word;
            for (int cls = 0; cls < 9; cls++) {
                int ch = cls / 3, cw = cls % 3;
                int nM = 0, extra = 0;
                for (int s = 0; s < 9; s++) {
                    int ih = s / 3, iw = s % 3;
                    bool valid = !((ch == 0 && ih == 0) || (ch == 2 && ih == 2) ||
                                   (cw == 0 && iw == 0) || (cw == 2 && iw == 2));
                    if (valid) nM += lens[s]; else extra += fpc[s];
                }
                gBase[((((size_t)conv << 8) | o) * 9 + cls) * JCH + j] = (u8)(nM + 2 * extra);
            }
        }
    }
}

// ---------------- channel-pack sign bits of the conv input ----------------
// MODE 0: bit = (x0 < 0); MODE 1: bit = (acc1*S + T < 0)  (BN1 sign; hardtanh keeps sign)
template<int MODE>
__global__ void k_pack(const float* __restrict__ x0) {
    int h = blockIdx.x, n = blockIdx.y;
    int lane = threadIdx.x & 31, warp = threadIdx.x >> 5;
    __shared__ u32 cmask[256];
    #pragma unroll 4
    for (int k = 0; k < 32; k++) {
        int c = warp * 32 + k;
        int gi = ((((n << 8) | c) << 10) | (h << 5)) | lane;
        bool neg;
        if (MODE == 0) neg = x0[gi] < 0.f;
        else           neg = fmaf((float)gAcc[gi], gS[c], gT[c]) < 0.f;
        u32 m = __ballot_sync(0xffffffffu, neg);
        if (lane == 0) cmask[c] = m;
    }
    __syncthreads();
    int w = threadIdx.x >> 3, wi = threadIdx.x & 7;   // pixel w, u32 word index
    u32 word = 0;
    #pragma unroll
    for (int b = 0; b < 32; b++)
        word |= (((cmask[(wi << 5) | b] >> w) & 1u) << b);
    gXc[(size_t)(((((n << 5) | h) << 5) | w)) * 8 + wi] = word;
}

// ---------------- binary conv + quantized-chunk accumulation + epilogue ----------------
// grid (h=32, n=32), 256 threads (thread = output channel o). Block = one image row.
template<int CONV>
__global__ void __launch_bounds__(256) k_conv(const float* __restrict__ x0res,
                                              float* __restrict__ outpre) {
    int h = blockIdx.x, n = blockIdx.y, o = threadIdx.x;
    __shared__ u64 sX[3][32][4];          // channel packs for rows h-1..h+1 (zero OOB)
    __shared__ ulonglong2 sA2[32][18];    // per-pixel chunk words (16B-aligned pairs)
    __shared__ float sOut[256 * 33];      // padded (o,p) staging for coalesced global I/O
    u64* sAf = (u64*)sA2;

    int gbase = (n << 18) + (h << 5);     // global base for (n, o=0, h, p=0)

    const u64* xc64 = (const u64*)gXc;
    for (int i = threadIdx.x; i < 384; i += 256) {
        int r = i >> 7, rem = i & 127;
        int hh = h - 1 + r;
        u64 v = 0;
        if ((unsigned)hh < 32u)
            v = xc64[(size_t)((((n << 5) + hh) << 5) + (rem >> 2)) * 4 + (rem & 3)];
        ((u64*)sX)[i] = v;
    }
    if (CONV == 1) {                      // stage residual coalesced (128B per warp)
        for (int i = threadIdx.x; i < 8192; i += 256)
            sOut[(i >> 5) * 33 + (i & 31)] = x0res[gbase + (i >> 5) * 1024 + (i & 31)];
    }
    __syncthreads();

    for (int i = threadIdx.x; i < 32 * JCH; i += 256) {
        int w = i / JCH, j = i - w * JCH;
        u64 word = 0; int pos = 0;
        #pragma unroll
        for (int s = 0; s < 9; s++) {
            int lo, len; fieldCS(j, s, lo, len);
            int nw = w + (s % 3) - 1;
            if ((unsigned)nw < 32u) {
                const u64* V = sX[s / 3][nw];
                int wq = lo >> 6, sh = lo & 63;
                u64 v = V[wq] >> sh;
                if (sh + len > 64) v |= V[wq + 1] << (64 - sh);
                v &= ((1ull << len) - 1ull);
                word |= v << pos;
            }
            pos += len;
        }
        sAf[w * JCH + j] = word;
    }
    __syncthreads();

    // weights for this o in registers (reused across 32 pixels)
    ulonglong2 Wr[18];
    #pragma unroll
    for (int j2 = 0; j2 < 18; j2++)
        Wr[j2] = *(const ulonglong2*)&gWt[(((size_t)CONV * 18 + j2) * 256 + o) * 2];

    int isum = 0, isq = 0;                // conv1: exact int partials
    float fsum = 0.f, fsq = 0.f;          // conv2: fp32 partials
    int clsh = (h == 0) ? 0 : ((h == 31) ? 2 : 1);

    auto emit = [&](int p, int acc) {
        acc = max(-254, min(254, acc));                       // accumulator clip
        if (CONV == 0) {
            sOut[o * 33 + p] = (float)acc;
            isum += acc; isq += acc * acc;
        } else {
            float pre = (float)acc + sOut[o * 33 + p];        // residual add (raw x0)
            sOut[o * 33 + p] = pre;
            fsum += pre; fsq = fmaf(pre, pre, fsq);
        }
    };
    auto borderAcc = [&](int p, int clsw) -> int {
        const u8* bp = &gBase[((((size_t)CONV << 8) | o) * 9 + (clsh * 3 + clsw)) * JCH];
        int acc = 0;
        #pragma unroll
        for (int j = 0; j < JCH; j++) {
            int pc = __popcll(sAf[p * JCH + j] ^ ((const u64*)Wr)[j]);
            int ps = (int)bp[j] - 2 * pc;                     // exact chunk psum
            if (ps & 1) ps += (ps & 2) ? 1 : -1;              // round-half-even quantizer
            acc += ps;
        }
        return acc;
    };

    if (clsh == 1) {
        emit(0, borderAcc(0, 0));
        #pragma unroll 2
        for (int p = 1; p < 31; p++) {
            int tot = 0;
            #pragma unroll
            for (int j2 = 0; j2 < 18; j2++) {
                ulonglong2 a = sA2[p][j2];
                tot += __popcll(a.x ^ Wr[j2].x);
                tot += __popcll(a.y ^ Wr[j2].y);
            }
            emit(p, 2304 - 2 * tot);       // interior: every chunk psum even, q == psum
        }
        emit(31, borderAcc(31, 2));
    } else {
        for (int p = 0; p < 32; p++) {
            int clsw = (p == 0) ? 0 : ((p == 31) ? 2 : 1);
            emit(p, borderAcc(p, clsw));
        }
    }

    if (CONV == 0) {
        atomicAdd(&gIsum[o], (u64)(long long)isum);
        atomicAdd(&gIsq[o], (u64)(long long)isq);
    } else {
        atomicAdd(&gDsum[o], (double)fsum);
        atomicAdd(&gDsq[o], (double)fsq);
    }

    __syncthreads();                      // coalesced writeback from staging
    for (int i = threadIdx.x; i < 8192; i += 256) {
        float v = sOut[(i >> 5) * 33 + (i & 31)];
        int gi = gbase + (i >> 5) * 1024 + (i & 31);
        if (CONV == 0) gAcc[gi] = (short)v;
        else           outpre[gi] = v;
    }
}

// ---------------- BN affine from batch stats ----------------
__global__ void k_bnparam(int mode, const float* __restrict__ gamma,
                          const float* __restrict__ beta) {
    int c = threadIdx.x;
    const double nelem = 32768.0;
    double mean, var;
    if (mode == 0) {
        double s = (double)(long long)gIsum[c];
        double q = (double)(long long)gIsq[c];
        mean = s / nelem; var = q / nelem - mean * mean;
    } else {
        mean = gDsum[c] / nelem; var = gDsq[c] / nelem - mean * mean;
    }
    double inv = 1.0 / sqrt(var + 1e-5);
    double g = (double)gamma[c];
    gS[c] = (float)(g * inv);
    gT[c] = (float)((double)beta[c] - mean * g * inv);
}

// ---------------- final: BN2 + hardtanh in place (float4), write reg ----------------
__global__ void k_final(float* __restrict__ out, const float* __restrict__ reg0,
                        int total, int write_reg) {
    int i = blockIdx.x * blockDim.x + threadIdx.x;
    if (i == 0 && write_reg) out[total] = reg0[0] + gReg;
    int nq = total >> 2;
    int stride = gridDim.x * blockDim.x;
    float4* o4 = (float4*)out;
    for (; i < nq; i += stride) {
        int c = (i >> 8) & 255;                 // (i*4 >> 10) & 255
        float S = gS[c], T = gT[c];
        float4 v = o4[i];
        v.x = fminf(1.f, fmaxf(-1.f, fmaf(v.x, S, T)));
        v.y = fminf(1.f, fmaxf(-1.f, fmaf(v.y, S, T)));
        v.z = fminf(1.f, fmaxf(-1.f, fmaf(v.z, S, T)));
        v.w = fminf(1.f, fmaxf(-1.f, fmaf(v.w, S, T)));
        o4[i] = v;
    }
}

extern "C" void kernel_launch(void* const* d_in, const int* in_sizes, int n_in,
                              void* d_out, int out_size) {
    const float* x0     = (const float*)d_in[0];
    const float* reg0   = (const float*)d_in[1];
    const float* w1     = (const float*)d_in[2];
    const float* gamma1 = (const float*)d_in[3];
    const float* beta1  = (const float*)d_in[4];
    const float* w2     = (const float*)d_in[5];
    const float* gamma2 = (const float*)d_in[6];
    const float* beta2  = (const float*)d_in[7];
    float* out = (float*)d_out;

    dim3 g(HH, NN);
    k_setup<<<2, 256>>>(w1, w2);
    k_pack<0><<<g, 256>>>(x0);
    k_conv<0><<<g, 256>>>((const float*)nullptr, (float*)nullptr);
    k_bnparam<<<1, 256>>>(0, gamma1, beta1);
    k_pack<1><<<g, 256>>>(x0);
    k_conv<1><<<g, 256>>>(x0, out);
    k_bnparam<<<1, 256>>>(1, gamma2, beta2);
    int total = TOTAL;
    k_final<<<2048, 256>>>(out, reg0, total, (out_size > total) ? 1 : 0);
    (void)in_sizes; (void)n_in;
}

// round 15
// speedup vs baseline: 1.7746x; 1.7746x over previous
#include <cuda_runtime.h>
#include <cuda_bf16.h>

typedef unsigned long long u64;
typedef unsigned int u32;
typedef unsigned char u8;

#define NN 32
#define CO 256
#define HH 32
#define PIX 1024
#define JCH 36
#define TOTAL (NN * CO * PIX)

// ---------------- static device scratch (no allocation) ----------------
__device__ u32 gXc[NN * PIX * 8];                 // per-pixel channel sign packs (256 bits)
__device__ u64 gWt2[2 * 2 * 18 * 256];            // weights [conv][half][jj][o]
__device__ u8  gBase[2 * 256 * 9 * JCH];          // base_j per (conv,o,cls,j)
__device__ short gAcc[TOTAL];                     // conv1 accumulator
__device__ u64 gIsum[CO], gIsq[CO];               // integer stats (conv1), two's complement
__device__ double gDsum[CO], gDsq[CO];            // float stats (conv2 + residual)
__device__ float gReg;                            // 3 * r_const

// chunk j covers features f in [64j, 64j+64), f = c*9 + s; fixed s -> contiguous c range
__device__ __forceinline__ void fieldCS(int j, int s, int& lo, int& len) {
    lo = (64 * j - s + 8) / 9;
    int hi = (64 * j + 63 - s) / 9;
    if (hi > 255) hi = 255;
    len = hi - lo + 1;
}

// ---------------- setup: zero stats, r_const, weight pack + base tables ----------------
__global__ void k_setup(const float* __restrict__ w1, const float* __restrict__ w2) {
    int t = blockIdx.x * 256 + threadIdx.x;       // grid: 2 x 256
    if (t < 256) { gIsum[t] = 0ull; gIsq[t] = 0ull; gDsum[t] = 0.0; gDsq[t] = 0.0; }
    if (t == 0) {
        // (q-psum)^2 == [nM_j(class) odd]  -> data-independent regularizer
        const int cnt[9] = {1, 30, 1, 30, 900, 30, 1, 30, 1};
        double r = 0.0;
        for (int j = 0; j < JCH; j++)
            for (int cls = 0; cls < 9; cls++) {
                int ch = cls / 3, cw = cls % 3;
                int nM = 0;
                for (int s = 0; s < 9; s++) {
                    int lo, len; fieldCS(j, s, lo, len);
                    int ih = s / 3, iw = s % 3;
                    bool valid = !((ch == 0 && ih == 0) || (ch == 2 && ih == 2) ||
                                   (cw == 0 && iw == 0) || (cw == 2 && iw == 2));
                    if (valid) nM += len;
                }
                if (nM & 1) r += (double)cnt[cls];
            }
        gReg = (float)(3.0 * r / 1024.0);
    }
    if (t < 512) {
        int conv = t >> 8, o = t & 255;
        const float* w = conv ? w2 : w1;
        for (int j = 0; j < JCH; j++) {
            u64 word = 0; int pos = 0;
            int fpc[9], lens[9];
            for (int s = 0; s < 9; s++) {
                int lo, len; fieldCS(j, s, lo, len);
                lens[s] = len;
                u32 f = 0;
                for (int i = 0; i < len; i++)
                    if (w[(size_t)o * 2304 + (size_t)(lo + i) * 9 + s] < 0.f) f |= 1u << i;
                fpc[s] = __popc(f);
                word |= ((u64)f) << pos;
                pos += len;
            }
            int half = (j >= 18), jj = j - 18 * half;
            gWt2[(((size_t)conv * 2 + half) * 18 + jj) * 256 + o] = word;
            for (int cls = 0; cls < 9; cls++) {
                int ch = cls / 3, cw = cls % 3;
                int nM = 0, extra = 0;
                for (int s = 0; s < 9; s++) {
                    int ih = s / 3, iw = s % 3;
                    bool valid = !((ch == 0 && ih == 0) || (ch == 2 && ih == 2) ||
                                   (cw == 0 && iw == 0) || (cw == 2 && iw == 2));
                    if (valid) nM += lens[s]; else extra += fpc[s];
                }
                gBase[((((size_t)conv << 8) | o) * 9 + cls) * JCH + j] = (u8)(nM + 2 * extra);
            }
        }
    }
}

// ---------------- channel-pack sign bits of the conv input ----------------
// MODE 0: bit = (x0 < 0); MODE 1: bit = (acc1*S + T < 0) (BN1 sign; hardtanh keeps sign)
template<int MODE>
__global__ void k_pack(const float* __restrict__ x0,
                       const float* __restrict__ gamma, const float* __restrict__ beta) {
    int h = blockIdx.x, n = blockIdx.y;
    int lane = threadIdx.x & 31, warp = threadIdx.x >> 5;
    __shared__ u32 cmask[256];
    __shared__ float sS[256], sT[256];
    if (MODE == 1) {
        int c = threadIdx.x;
        double mean = (double)(long long)gIsum[c] / 32768.0;
        double var  = (double)(long long)gIsq[c] / 32768.0 - mean * mean;
        double g = (double)gamma[c] / sqrt(var + 1e-5);
        sS[c] = (float)g;
        sT[c] = (float)((double)beta[c] - mean * g);
        __syncthreads();
    }
    for (int k = 0; k < 32; k++) {
        int c = warp * 32 + k;
        int gi = ((((n << 8) | c) << 10) | (h << 5)) | lane;
        bool neg;
        if (MODE == 0) neg = x0[gi] < 0.f;
        else           neg = fmaf((float)gAcc[gi], sS[c], sT[c]) < 0.f;
        u32 m = __ballot_sync(0xffffffffu, neg);
        if (lane == 0) cmask[c] = m;
    }
    __syncthreads();
    int w = threadIdx.x >> 3, wi = threadIdx.x & 7;
    u32 word = 0;
    #pragma unroll
    for (int b = 0; b < 32; b++)
        word |= (((cmask[(wi << 5) | b] >> w) & 1u) << b);
    gXc[(size_t)(((((n << 5) | h) << 5) | w)) * 8 + wi] = word;
}

// ---------------- binary conv, half-split reduction ----------------
// grid (h=32, n=32), 512 threads: thread = (o = tid>>1, half = tid&1).
// Half owns chunks [18*half, 18*half+18) == channels [128*half, 128*half+128).
template<int CONV>
__global__ void __launch_bounds__(512) k_conv(const float* __restrict__ x0res,
                                              float* __restrict__ outpre) {
    int h = blockIdx.x, n = blockIdx.y;
    int tid = threadIdx.x;
    int o = tid >> 1, half = tid & 1;
    __shared__ u64 sX[3][32][4];           // channel packs rows h-1..h+1 (zero OOB)
    __shared__ ulonglong2 sA2[32][2][9];   // chunk words [pixel][half][jj pairs]
    u64* sAf = (u64*)sA2;

    const u64* xc64 = (const u64*)gXc;
    for (int i = tid; i < 384; i += 512) {
        int r = i >> 7, rem = i & 127;
        int hh = h - 1 + r;
        u64 v = 0;
        if ((unsigned)hh < 32u)
            v = xc64[(size_t)((((n << 5) + hh) << 5) + (rem >> 2)) * 4 + (rem & 3)];
        ((u64*)sX)[i] = v;
    }
    __syncthreads();

    for (int i = tid; i < 32 * JCH; i += 512) {
        int p = i / JCH, j = i - p * JCH;
        u64 word = 0; int pos = 0;
        #pragma unroll
        for (int s = 0; s < 9; s++) {
            int lo, len; fieldCS(j, s, lo, len);
            int nw = p + (s % 3) - 1;
            if ((unsigned)nw < 32u) {
                const u64* V = sX[s / 3][nw];
                int wq = lo >> 6, sh = lo & 63;
                u64 v = V[wq] >> sh;
                if (sh + len > 64) v |= V[wq + 1] << (64 - sh);
                v &= ((1ull << len) - 1ull);
                word |= v << pos;
            }
            pos += len;
        }
        int jh = (j >= 18), jj = j - 18 * jh;
        sAf[(p * 2 + jh) * 18 + jj] = word;
    }
    __syncthreads();

    // this thread's 18 weight words (its half of the reduction)
    u64 Wr[18];
    #pragma unroll
    for (int jj = 0; jj < 18; jj++)
        Wr[jj] = gWt2[(((size_t)CONV * 2 + half) * 18 + jj) * 256 + o];

    int isum = 0, isq = 0;
    float fsum = 0.f, fsq = 0.f;
    int clsh = (h == 0) ? 0 : ((h == 31) ? 2 : 1);
    size_t gb = ((size_t)((n << 8) | o) << 10) | (size_t)(h << 5);

    auto interiorT = [&](int p) -> int {       // partial popc over this half
        const ulonglong2* A = &sA2[p][half][0];
        int t = 0;
        #pragma unroll
        for (int j2 = 0; j2 < 9; j2++) {
            ulonglong2 a = A[j2];
            t += __popcll(a.x ^ Wr[2 * j2]);
            t += __popcll(a.y ^ Wr[2 * j2 + 1]);
        }
        return t;
    };
    auto borderQ = [&](int p, int cls) -> int { // quantized partial over this half
        const u8* bp = &gBase[((((size_t)CONV << 8) | o) * 9 + cls) * JCH + half * 18];
        const u64* A = &sAf[(p * 2 + half) * 18];
        int acc = 0;
        #pragma unroll
        for (int jj = 0; jj < 18; jj++) {
            int pc = __popcll(A[jj] ^ Wr[jj]);
            int ps = (int)bp[jj] - 2 * pc;                // exact chunk psum
            if (ps & 1) ps += (ps & 2) ? 1 : -1;          // round-half-even quantizer
            acc += ps;
        }
        return acc;
    };

    for (int pb = 0; pb < 32; pb += 4) {          // explicit 4-pixel groups:
        float4 buf;                               // float4 lanes indexed by constant q
        if (CONV == 1 && half == 0)
            buf = *(const float4*)&x0res[gb + (size_t)pb];   // residual (raw x0)
        #pragma unroll
        for (int q = 0; q < 4; q++) {
            int p = pb + q;
            int acc;
            if (clsh == 1 && p > 0 && p < 31) {
                int t = interiorT(p);
                t += __shfl_xor_sync(0xffffffffu, t, 1);
                acc = 2304 - 2 * t;               // interior: chunk psums even, q == psum
            } else {
                int clsw = (p == 0) ? 0 : ((p == 31) ? 2 : 1);
                int v = borderQ(p, clsh * 3 + clsw);
                acc = v + __shfl_xor_sync(0xffffffffu, v, 1);
            }
            acc = max(-254, min(254, acc));       // accumulator clip
            if (half == 0) {
                if (CONV == 0) {
                    isum += acc; isq += acc * acc;
                    ((float*)&buf)[q] = (float)acc;       // q is compile-time constant
                } else {
                    float pre = (float)acc + ((float*)&buf)[q];
                    ((float*)&buf)[q] = pre;
                    fsum += pre; fsq = fmaf(pre, pre, fsq);
                }
            }
        }
        if (half == 0) {
            if (CONV == 0) {
                short4 s4 = { (short)buf.x, (short)buf.y, (short)buf.z, (short)buf.w };
                *(short4*)&gAcc[gb + (size_t)pb] = s4;
            } else {
                *(float4*)&outpre[gb + (size_t)pb] = buf;
            }
        }
    }

    if (half == 0) {
        if (CONV == 0) {
            atomicAdd(&gIsum[o], (u64)(long long)isum);
            atomicAdd(&gIsq[o], (u64)(long long)isq);
        } else {
            atomicAdd(&gDsum[o], (double)fsum);
            atomicAdd(&gDsq[o], (double)fsq);
        }
    }
}

// ---------------- final: BN2 + hardtanh (affine recomputed per block), write reg ----------------
__global__ void k_final(float* __restrict__ out, const float* __restrict__ reg0,
                        const float* __restrict__ gamma, const float* __restrict__ beta,
                        int total, int write_reg) {
    __shared__ float sS[256], sT[256];
    if (threadIdx.x < 256) {
        int c = threadIdx.x;
        double mean = gDsum[c] / 32768.0;
        double var  = gDsq[c] / 32768.0 - mean * mean;
        double g = (double)gamma[c] / sqrt(var + 1e-5);
        sS[c] = (float)g;
        sT[c] = (float)((double)beta[c] - mean * g);
    }
    __syncthreads();
    int i = blockIdx.x * blockDim.x + threadIdx.x;
    if (i == 0 && write_reg) out[total] = reg0[0] + gReg;
    int nq = total >> 2;
    int stride = gridDim.x * blockDim.x;
    float4* o4 = (float4*)out;
    for (; i < nq; i += stride) {
        int c = (i >> 8) & 255;
        float S = sS[c], T = sT[c];
        float4 v = o4[i];
        v.x = fminf(1.f, fmaxf(-1.f, fmaf(v.x, S, T)));
        v.y = fminf(1.f, fmaxf(-1.f, fmaf(v.y, S, T)));
        v.z = fminf(1.f, fmaxf(-1.f, fmaf(v.z, S, T)));
        v.w = fminf(1.f, fmaxf(-1.f, fmaf(v.w, S, T)));
        o4[i] = v;
    }
}

extern "C" void kernel_launch(void* const* d_in, const int* in_sizes, int n_in,
                              void* d_out, int out_size) {
    const float* x0     = (const float*)d_in[0];
    const float* reg0   = (const float*)d_in[1];
    const float* w1     = (const float*)d_in[2];
    const float* gamma1 = (const float*)d_in[3];
    const float* beta1  = (const float*)d_in[4];
    const float* w2     = (const float*)d_in[5];
    const float* gamma2 = (const float*)d_in[6];
    const float* beta2  = (const float*)d_in[7];
    float* out = (float*)d_out;

    dim3 g(HH, NN);
    k_setup<<<2, 256>>>(w1, w2);
    k_pack<0><<<g, 256>>>(x0, gamma1, beta1);
    k_conv<0><<<g, 512>>>((const float*)nullptr, (float*)nullptr);
    k_pack<1><<<g, 256>>>(x0, gamma1, beta1);
    k_conv<1><<<g, 512>>>(x0, out);
    int total = TOTAL;
    k_final<<<2048, 256>>>(out, reg0, gamma2, beta2, total, (out_size > total) ? 1 : 0);
    (void)in_sizes; (void)n_in;
}